// round 12
// baseline (speedup 1.0000x reference)
#include <cuda_runtime.h>
#include <cuda_bf16.h>
#include <math.h>
#include <stdint.h>

// ---------------- problem constants ----------------
#define B_    16
#define C_    64
#define HW    441
#define NCLS  10
#define M_    2205
#define MT    128            // m tile
#define NT    18             // m tiles (18*128 = 2304)
#define MP    2304
#define ROWS  7056
#define RT    128            // row tile
#define RB    56             // row blocks (56*128 = 7168)
#define ROWSP 7168
#define NQU   7168           // q rows (padded)
#define NSU   23040          // s rows (10*2304)
#define NU    (NQU + NSU)    // 30208 -> 944 blocks of 32 rows

// ---------------- device scratch (no allocation allowed) ----------------
__device__ __align__(16) __nv_bfloat16 g_qh[ROWSP * C_];       // normalized queries [row][k]
__device__ __align__(16) __nv_bfloat16 g_sh[NCLS * MP * C_];   // normalized support [n][m][k]
__device__ float g_part[NCLS * RB * 2];                        // per-(n,block) b-segment sums

typedef uint32_t u32;

// ---------------- PTX helpers (all plain-sm_103-safe) ----------------
__device__ __forceinline__ u32 smem_u32(const void* p){
    u32 a;
    asm("{ .reg .u64 t; cvta.to.shared.u64 t, %1; cvt.u32.u64 %0, t; }" : "=r"(a) : "l"(p));
    return a;
}
// Scalar branchless sorted top-3 insert.
__device__ __forceinline__ void ins3(float v, float& a, float& b, float& c){
    float na = fmaxf(a, v);
    float nb = fmaxf(b, fminf(a, v));
    float nc = fmaxf(c, fminf(b, v));
    a = na; b = nb; c = nc;
}
// Packed bf16x2 top-3 insert: two independent streams per register.
__device__ __forceinline__ void ins3pb(__nv_bfloat162 v, __nv_bfloat162& a,
                                       __nv_bfloat162& b, __nv_bfloat162& c){
    __nv_bfloat162 na = __hmax2(a, v);
    __nv_bfloat162 nb = __hmax2(b, __hmin2(a, v));
    __nv_bfloat162 nc = __hmax2(c, __hmin2(b, v));
    a = na; b = nb; c = nc;
}

#define SW(off) ((u32)(off) ^ (((u32)(off) >> 3) & 0x70u))

#define CPA16(dst, src) \
    asm volatile("cp.async.cg.shared.global [%0], [%1], 16;" :: "r"(dst), "l"(src) : "memory")
#define CPA_COMMIT() asm volatile("cp.async.commit_group;" ::: "memory")

#define LDMX4(r, a) \
    asm volatile("ldmatrix.sync.aligned.m8n8.x4.shared.b16 {%0,%1,%2,%3}, [%4];" \
        : "=r"((r)[0]), "=r"((r)[1]), "=r"((r)[2]), "=r"((r)[3]) : "r"(a))

#define MMA16816(c, a, b0, b1) \
    asm volatile("mma.sync.aligned.m16n8k16.row.col.f32.bf16.bf16.f32 " \
        "{%0,%1,%2,%3}, {%4,%5,%6,%7}, {%8,%9}, {%0,%1,%2,%3};" \
        : "+f"((c)[0]), "+f"((c)[1]), "+f"((c)[2]), "+f"((c)[3]) \
        : "r"((a)[0]), "r"((a)[1]), "r"((a)[2]), "r"((a)[3]), "r"(b0), "r"(b1))

// ---------------------------------------------------------------------------
// Normalize, 8 threads per descriptor row (sub-warp shfl reduce, 16B stores).
// Unit u in [0,NQU): query row u -> g_qh.  u in [NQU,NU): support -> g_sh.
// Padding rows load zeros (no divergence: 0 * 1e12 = 0).
// grid = 944 blocks x 256 threads (32 rows/block).
// ---------------------------------------------------------------------------
__global__ void norm_kernel(const float* __restrict__ x1, const float* __restrict__ x2){
    const int u   = blockIdx.x * 32 + (threadIdx.x >> 3);
    const int sub = threadIdx.x & 7;             // c-chunk: covers c = sub*8 .. sub*8+7

    float v[8];
    __nv_bfloat16* outp;
    if (u < NQU){
        outp = g_qh + (size_t)u * C_ + sub * 8;
        if (u >= ROWS){
            #pragma unroll
            for (int j = 0; j < 8; j++) v[j] = 0.f;
        } else {
            int b  = u / HW;
            int qi = u - b * HW;
            const float* p = x1 + (size_t)b * C_ * HW + qi + (size_t)(sub * 8) * HW;
            #pragma unroll
            for (int j = 0; j < 8; j++) v[j] = p[j * HW];
        }
    } else {
        int w = u - NQU;
        int n = w / MP;
        int m = w - n * MP;
        outp = g_sh + (size_t)w * C_ + sub * 8;
        if (m >= M_){
            #pragma unroll
            for (int j = 0; j < 8; j++) v[j] = 0.f;
        } else {
            const float* p = x2 + (size_t)n * C_ * M_ + m + (size_t)(sub * 8) * M_;
            #pragma unroll
            for (int j = 0; j < 8; j++) v[j] = p[j * M_];
        }
    }
    float ss = 0.f;
    #pragma unroll
    for (int j = 0; j < 8; j++) ss += v[j] * v[j];
    #pragma unroll
    for (int o = 1; o <= 4; o <<= 1) ss += __shfl_xor_sync(0xffffffffu, ss, o);
    float inv = 1.f / fmaxf(sqrtf(ss), 1e-12f);

    __nv_bfloat162 o2[4];
    #pragma unroll
    for (int j = 0; j < 4; j++)
        o2[j] = __floats2bfloat162_rn(v[2*j] * inv, v[2*j+1] * inv);
    *reinterpret_cast<uint4*>(outp) = *reinterpret_cast<uint4*>(o2);
}

// ---------------------------------------------------------------------------
// Main: mma.sync bf16 GEMM (CTA 128x128, K=64) + fused packed-bf16 top-3.
// grid = (56, 10), block = 256 (8 warps). Warp tile 32 rows x 64 cols as one
// 8-step register-pipelined sequence (2 passes x 4 ks); B fragments are
// double-buffered in registers so LDSM latency hides under HMMA issue.
// cp.async double-buffered B tiles; A tile resident, fragments hoisted.
// smem: [0,16K) A (swizzled) -> reused as merge/reduce buf; [16K..48K) B0/B1.
// mma frag: c[q] -> row = lane>>2 (+8 for q>=2), col = 2*(lane&3) + (q&1).
// ---------------------------------------------------------------------------
__global__ void __launch_bounds__(256, 2) sim_mma_kernel(){
    __shared__ __align__(16) char smem[49152];
    const u32 sb   = smem_u32(smem);
    const int tid  = threadIdx.x;
    const int wid  = tid >> 5;
    const int lane = tid & 31;
    const int n    = blockIdx.y;
    const int blk  = blockIdx.x;
    const int row0 = blk * RT;
    const int mrow = (wid & 3) * 32;          // warp's row offset in tile
    const int ncol = (wid >> 2) * 64;         // warp's col offset in tile

    const char* gA = (const char*)g_qh + (size_t)row0 * C_ * 2;
    const char* gB = (const char*)g_sh + (size_t)n * MP * C_ * 2;

    // Prologue: group0 = {A, B0}; group1 = {B1}. 16KB each = 1024 16B chunks.
    #pragma unroll
    for (int i = 0; i < 4; i++){
        int j = tid + i * 256;
        CPA16(sb + SW(j * 16), gA + (size_t)j * 16);
    }
    #pragma unroll
    for (int i = 0; i < 4; i++){
        int j = tid + i * 256;
        CPA16(sb + 16384u + SW(j * 16), gB + (size_t)j * 16);
    }
    CPA_COMMIT();
    #pragma unroll
    for (int i = 0; i < 4; i++){
        int j = tid + i * 256;
        CPA16(sb + 32768u + SW(j * 16), gB + 16384 + (size_t)j * 16);
    }
    CPA_COMMIT();

    const int rA    = lane & 15;              // ldmatrix row-within-frag
    const int khalf = (lane >> 4) * 8;        // ldmatrix k-half
    const u32 swx   = (u32)((rA & 7) << 4);   // SW128 xor term (row low bits)

    // A is tile-loop invariant: hoist all A fragments (32 regs).
    asm volatile("cp.async.wait_group 1;" ::: "memory");
    __syncthreads();
    u32 af[4][8];
    #pragma unroll
    for (int ks = 0; ks < 4; ks++){
        const u32 colb  = ((u32)((ks * 16 + khalf) * 2)) ^ swx;
        const u32 aaddr = sb + (u32)((mrow + rA) * 128) + colb;
        LDMX4(af[ks],     aaddr);
        LDMX4(af[ks] + 4, aaddr + 2048u);
    }

    // Packed top-3 state: slot s = mf*2 + half; two col-streams per slot.
    const __nv_bfloat162 NI2 = __floats2bfloat162_rn(-INFINITY, -INFINITY);
    __nv_bfloat162 p0[4], p1[4], p2[4];
    #pragma unroll
    for (int s = 0; s < 4; s++){ p0[s] = NI2; p1[s] = NI2; p2[s] = NI2; }

    for (int t = 0; t < NT; t++){
        if (t == NT - 1) asm volatile("cp.async.wait_group 0;" ::: "memory");
        else             asm volatile("cp.async.wait_group 1;" ::: "memory");
        __syncthreads();
        const u32 bbase = sb + ((t & 1) ? 32768u : 16384u) + (u32)((ncol + rA) * 128);

        // ldB: step = pass*4 + ks -> fragment pair {bA, bB} for 32 cols.
        auto ldB = [&](int step, u32* dst){
            const int pass = step >> 2, ks = step & 3;
            const u32 colb  = ((u32)((ks * 16 + khalf) * 2)) ^ swx;
            const u32 baddr = bbase + (u32)(pass * 32 * 128) + colb;
            LDMX4(dst,     baddr);
            LDMX4(dst + 4, baddr + 2048u);
        };
        auto mma8 = [&](float (&c)[2][4][4], int ks, u32* bf){
            MMA16816(c[0][0], af[ks],     bf[0], bf[2]);
            MMA16816(c[0][1], af[ks],     bf[1], bf[3]);
            MMA16816(c[0][2], af[ks],     bf[4], bf[6]);
            MMA16816(c[0][3], af[ks],     bf[5], bf[7]);
            MMA16816(c[1][0], af[ks] + 4, bf[0], bf[2]);
            MMA16816(c[1][1], af[ks] + 4, bf[1], bf[3]);
            MMA16816(c[1][2], af[ks] + 4, bf[4], bf[6]);
            MMA16816(c[1][3], af[ks] + 4, bf[5], bf[7]);
        };
        auto epi_full = [&](float (&c)[2][4][4]){
            #pragma unroll
            for (int mf = 0; mf < 2; mf++)
                #pragma unroll
                for (int nf = 0; nf < 4; nf++){
                    ins3pb(__floats2bfloat162_rn(c[mf][nf][0], c[mf][nf][1]),
                           p0[mf*2],   p1[mf*2],   p2[mf*2]);
                    ins3pb(__floats2bfloat162_rn(c[mf][nf][2], c[mf][nf][3]),
                           p0[mf*2+1], p1[mf*2+1], p2[mf*2+1]);
                }
        };
        auto epi_mask = [&](float (&c)[2][4][4], int pass){
            const int rem = M_ - (NT - 1) * MT;   // 29 valid cols in last tile
            #pragma unroll
            for (int nf = 0; nf < 4; nf++){
                const int col0 = ncol + pass * 32 + nf * 8 + (lane & 3) * 2;
                const bool v0 = col0     < rem;
                const bool v1 = col0 + 1 < rem;
                #pragma unroll
                for (int mf = 0; mf < 2; mf++){
                    ins3pb(__floats2bfloat162_rn(v0 ? c[mf][nf][0] : -INFINITY,
                                                 v1 ? c[mf][nf][1] : -INFINITY),
                           p0[mf*2],   p1[mf*2],   p2[mf*2]);
                    ins3pb(__floats2bfloat162_rn(v0 ? c[mf][nf][2] : -INFINITY,
                                                 v1 ? c[mf][nf][3] : -INFINITY),
                           p0[mf*2+1], p1[mf*2+1], p2[mf*2+1]);
                }
            }
        };

        u32 f0[8], f1[8];
        ldB(0, f0);

        float c0[2][4][4];
        #pragma unroll
        for (int mf = 0; mf < 2; mf++)
            #pragma unroll
            for (int nf = 0; nf < 4; nf++)
                #pragma unroll
                for (int q = 0; q < 4; q++) c0[mf][nf][q] = 0.f;
        ldB(1, f1); mma8(c0, 0, f0);
        ldB(2, f0); mma8(c0, 1, f1);
        ldB(3, f1); mma8(c0, 2, f0);
        ldB(4, f0); mma8(c0, 3, f1);
        if (t < NT - 1) epi_full(c0); else epi_mask(c0, 0);

        float c1[2][4][4];
        #pragma unroll
        for (int mf = 0; mf < 2; mf++)
            #pragma unroll
            for (int nf = 0; nf < 4; nf++)
                #pragma unroll
                for (int q = 0; q < 4; q++) c1[mf][nf][q] = 0.f;
        ldB(5, f1); mma8(c1, 0, f0);
        ldB(6, f0); mma8(c1, 1, f1);
        ldB(7, f1); mma8(c1, 2, f0);
                    mma8(c1, 3, f1);

        // All B-smem reads for this tile are consumed; refill this buffer.
        __syncthreads();
        if (t + 2 < NT){
            const u32 dst = sb + ((t & 1) ? 32768u : 16384u);
            #pragma unroll
            for (int i = 0; i < 4; i++){
                int j = tid + i * 256;
                CPA16(dst + SW(j * 16), gB + (size_t)(t + 2) * 16384 + (size_t)j * 16);
            }
            CPA_COMMIT();
        }
        if (t < NT - 1) epi_full(c1); else epi_mask(c1, 1);
    }

    // Collapse packed streams -> scalar top-3 per slot.
    float s0[4], s1[4], s2[4];
    #pragma unroll
    for (int s = 0; s < 4; s++){
        s0[s] = -INFINITY; s1[s] = -INFINITY; s2[s] = -INFINITY;
        float2 a;
        a = __bfloat1622float2(p0[s]); ins3(a.x, s0[s], s1[s], s2[s]); ins3(a.y, s0[s], s1[s], s2[s]);
        a = __bfloat1622float2(p1[s]); ins3(a.x, s0[s], s1[s], s2[s]); ins3(a.y, s0[s], s1[s], s2[s]);
        a = __bfloat1622float2(p2[s]); ins3(a.x, s0[s], s1[s], s2[s]); ins3(a.y, s0[s], s1[s], s2[s]);
    }
    // Merge across the 4 lanes sharing each row.
    #pragma unroll
    for (int off = 1; off <= 2; off <<= 1){
        #pragma unroll
        for (int s = 0; s < 4; s++){
            float u0 = __shfl_xor_sync(0xffffffffu, s0[s], off);
            float u1 = __shfl_xor_sync(0xffffffffu, s1[s], off);
            float u2 = __shfl_xor_sync(0xffffffffu, s2[s], off);
            ins3(u0, s0[s], s1[s], s2[s]);
            ins3(u1, s0[s], s1[s], s2[s]);
            ins3(u2, s0[s], s1[s], s2[s]);
        }
    }
    // Merge the two column-half warps via smem (A region is dead now).
    float* mrg  = reinterpret_cast<float*>(smem);            // 384 floats
    float* rsum = reinterpret_cast<float*>(smem + 2048);     // 128 floats
    if (wid >= 4 && (lane & 3) == 0){
        #pragma unroll
        for (int s = 0; s < 4; s++){
            int row = mrow + (s >> 1) * 16 + (s & 1) * 8 + (lane >> 2);
            mrg[row * 3 + 0] = s0[s];
            mrg[row * 3 + 1] = s1[s];
            mrg[row * 3 + 2] = s2[s];
        }
    }
    __syncthreads();
    if (wid < 4 && (lane & 3) == 0){
        #pragma unroll
        for (int s = 0; s < 4; s++){
            int row = mrow + (s >> 1) * 16 + (s & 1) * 8 + (lane >> 2);
            ins3(mrg[row * 3 + 0], s0[s], s1[s], s2[s]);
            ins3(mrg[row * 3 + 1], s0[s], s1[s], s2[s]);
            ins3(mrg[row * 3 + 2], s0[s], s1[s], s2[s]);
            rsum[row] = s0[s] + s1[s] + s2[s];   // padded rows naturally give 0
        }
    }
    __syncthreads();
    // Block reduction split by batch-image boundary (<=1 boundary: 441 > 128).
    if (wid == 0){
        const int b0    = row0 / HW;
        const int split = (b0 + 1) * HW - row0;   // may be >= 128 (no boundary)
        float lo = 0.f, hi = 0.f;
        #pragma unroll
        for (int i = 0; i < 4; i++){
            int r = lane + 32 * i;
            float v = rsum[r];
            if (r < split) lo += v; else hi += v;
        }
        #pragma unroll
        for (int o = 16; o; o >>= 1){
            lo += __shfl_down_sync(0xffffffffu, lo, o);
            hi += __shfl_down_sync(0xffffffffu, hi, o);
        }
        if (lane == 0){
            g_part[(n * RB + blk) * 2 + 0] = lo;
            g_part[(n * RB + blk) * 2 + 1] = hi;   // belongs to b0+1 (dropped if 16)
        }
    }
}

// ---------------------------------------------------------------------------
// out[b][n] = sum of partials mapping to b. One block.
// ---------------------------------------------------------------------------
__global__ void reduce_out_kernel(float* __restrict__ out){
    const int tid = threadIdx.x;
    if (tid >= B_ * NCLS) return;
    const int b = tid / NCLS;
    const int n = tid % NCLS;
    float s = 0.f;
    #pragma unroll 8
    for (int blk = 0; blk < RB; blk++){
        int b0 = (blk * RT) / HW;
        float v0 = g_part[(n * RB + blk) * 2 + 0];
        float v1 = g_part[(n * RB + blk) * 2 + 1];
        if (b0 == b)     s += v0;
        if (b0 + 1 == b) s += v1;
    }
    out[tid] = s;
}

extern "C" void kernel_launch(void* const* d_in, const int* in_sizes, int n_in,
                              void* d_out, int out_size){
    const float* x1 = (const float*)d_in[0];   // [16,64,21,21] fp32
    const float* x2 = (const float*)d_in[1];   // [10,64,2205]  fp32
    float* out = (float*)d_out;                // [16,10] fp32

    norm_kernel<<<NU / 32, 256>>>(x1, x2);
    sim_mma_kernel<<<dim3(RB, NCLS), 256>>>();
    reduce_out_kernel<<<1, 192>>>(out);
}

// round 13
// speedup vs baseline: 1.0099x; 1.0099x over previous
#include <cuda_runtime.h>
#include <cuda_bf16.h>
#include <math.h>
#include <stdint.h>

// ---------------- problem constants ----------------
#define B_    16
#define C_    64
#define HW    441
#define NCLS  10
#define M_    2205
#define MT    128            // m tile
#define NT    18             // m tiles (18*128 = 2304)
#define MP    2304
#define ROWS  7056
#define RT    128            // row tile
#define RB    56             // row blocks (56*128 = 7168)
#define ROWSP 7168
#define NQU   7168           // q rows (padded)
#define NSU   23040          // s rows (10*2304)
#define NU    (NQU + NSU)    // 30208 -> 944 blocks of 32 rows
#define TILEB 16384          // bytes per 128-row swizzled tile

// ---------------- device scratch (no allocation allowed) ----------------
// Both tensors stored PRE-SWIZZLED in 16KB tile units so a contiguous
// cp.async.bulk reproduces the SW128 smem image ldmatrix expects.
__device__ __align__(16) __nv_bfloat16 g_qh[ROWSP * C_];       // [blk][swizzled 16KB]
__device__ __align__(16) __nv_bfloat16 g_sh[NCLS * MP * C_];   // [n][tile][swizzled 16KB]
__device__ float g_part[NCLS * RB * 2];                        // per-(n,block) b-segment sums

typedef uint32_t u32;

// ---------------- PTX helpers (all plain-sm_103-safe) ----------------
__device__ __forceinline__ u32 smem_u32(const void* p){
    u32 a;
    asm("{ .reg .u64 t; cvta.to.shared.u64 t, %1; cvt.u32.u64 %0, t; }" : "=r"(a) : "l"(p));
    return a;
}
// Scalar branchless sorted top-3 insert.
__device__ __forceinline__ void ins3(float v, float& a, float& b, float& c){
    float na = fmaxf(a, v);
    float nb = fmaxf(b, fminf(a, v));
    float nc = fmaxf(c, fminf(b, v));
    a = na; b = nb; c = nc;
}
// Packed bf16x2 top-3 insert: two independent streams per register.
__device__ __forceinline__ void ins3pb(__nv_bfloat162 v, __nv_bfloat162& a,
                                       __nv_bfloat162& b, __nv_bfloat162& c){
    __nv_bfloat162 na = __hmax2(a, v);
    __nv_bfloat162 nb = __hmax2(b, __hmin2(a, v));
    __nv_bfloat162 nc = __hmax2(c, __hmin2(b, v));
    a = na; b = nb; c = nc;
}

#define SW(off) ((u32)(off) ^ (((u32)(off) >> 3) & 0x70u))

#define MBAR_INIT(mbar, cnt) \
    asm volatile("mbarrier.init.shared.b64 [%0], %1;" :: "r"(mbar), "r"(cnt) : "memory")
#define EXPECT_TX(mbar, nb) \
    asm volatile("mbarrier.arrive.expect_tx.shared.b64 _, [%0], %1;" :: "r"(mbar), "r"(nb) : "memory")
#define BULK_G2S(dst, src, nb, mbar) \
    asm volatile("cp.async.bulk.shared::cluster.global.mbarrier::complete_tx::bytes " \
                 "[%0], [%1], %2, [%3];" \
                 :: "r"(dst), "l"(src), "r"(nb), "r"(mbar) : "memory")

__device__ __forceinline__ void mbar_wait(u32 mbar, u32 parity){
    asm volatile(
        "{\n\t.reg .pred P;\n"
        "LW_%=:\n\t"
        "mbarrier.try_wait.parity.acquire.cta.shared::cta.b64 P, [%0], %1, 0x989680;\n\t"
        "@P bra LD_%=;\n\t"
        "bra LW_%=;\n"
        "LD_%=:\n\t}"
        :: "r"(mbar), "r"(parity) : "memory");
}

#define LDMX4(r, a) \
    asm volatile("ldmatrix.sync.aligned.m8n8.x4.shared.b16 {%0,%1,%2,%3}, [%4];" \
        : "=r"((r)[0]), "=r"((r)[1]), "=r"((r)[2]), "=r"((r)[3]) : "r"(a))

#define MMA16816(c, a, b0, b1) \
    asm volatile("mma.sync.aligned.m16n8k16.row.col.f32.bf16.bf16.f32 " \
        "{%0,%1,%2,%3}, {%4,%5,%6,%7}, {%8,%9}, {%0,%1,%2,%3};" \
        : "+f"((c)[0]), "+f"((c)[1]), "+f"((c)[2]), "+f"((c)[3]) \
        : "r"((a)[0]), "r"((a)[1]), "r"((a)[2]), "r"((a)[3]), "r"(b0), "r"(b1))

// smem layout (dynamic): [0,8) mbarA, [8,16) mb0, [16,24) mb1,
// [1024,17408) A tile (reused as merge buf), [17408,33792) B0, [33792,50176) B1.
#define OFF_MBA  0u
#define OFF_MB0  8u
#define OFF_MB1  16u
#define OFF_A    1024u
#define OFF_B0   17408u
#define OFF_B1   33792u
#define SMEM_REQ 50176

// ---------------------------------------------------------------------------
// Normalize, 8 threads per descriptor row; OUTPUT IS SWIZZLED per 16KB tile.
// Each thread writes one 16B chunk -> per row the 8 chunks cover a permuted
// 128B segment (still fully coalesced).
// ---------------------------------------------------------------------------
__global__ void norm_kernel(const float* __restrict__ x1, const float* __restrict__ x2){
    const int u   = blockIdx.x * 32 + (threadIdx.x >> 3);
    const int sub = threadIdx.x & 7;             // c-chunk: c = sub*8 .. sub*8+7

    float v[8];
    char* outp;
    if (u < NQU){
        const int blk = u >> 7, r = u & 127;
        outp = (char*)g_qh + (size_t)blk * TILEB + SW(r * 128 + sub * 16);
        if (u >= ROWS){
            #pragma unroll
            for (int j = 0; j < 8; j++) v[j] = 0.f;
        } else {
            int b  = u / HW;
            int qi = u - b * HW;
            const float* p = x1 + (size_t)b * C_ * HW + qi + (size_t)(sub * 8) * HW;
            #pragma unroll
            for (int j = 0; j < 8; j++) v[j] = p[j * HW];
        }
    } else {
        int w = u - NQU;
        int n = w / MP;
        int m = w - n * MP;
        const int t = m >> 7, r = m & 127;
        outp = (char*)g_sh + (size_t)(n * NT + t) * TILEB + SW(r * 128 + sub * 16);
        if (m >= M_){
            #pragma unroll
            for (int j = 0; j < 8; j++) v[j] = 0.f;
        } else {
            const float* p = x2 + (size_t)n * C_ * M_ + m + (size_t)(sub * 8) * M_;
            #pragma unroll
            for (int j = 0; j < 8; j++) v[j] = p[j * M_];
        }
    }
    float ss = 0.f;
    #pragma unroll
    for (int j = 0; j < 8; j++) ss += v[j] * v[j];
    #pragma unroll
    for (int o = 1; o <= 4; o <<= 1) ss += __shfl_xor_sync(0xffffffffu, ss, o);
    float inv = 1.f / fmaxf(sqrtf(ss), 1e-12f);

    __nv_bfloat162 o2[4];
    #pragma unroll
    for (int j = 0; j < 4; j++)
        o2[j] = __floats2bfloat162_rn(v[2*j] * inv, v[2*j+1] * inv);
    *reinterpret_cast<uint4*>(outp) = *reinterpret_cast<uint4*>(o2);
}

// ---------------------------------------------------------------------------
// Main: mma.sync bf16 GEMM (CTA 128x128, K=64) + fused packed-bf16 top-3.
// B tiles arrive via ONE cp.async.bulk (16KB) per tile + mbarrier, removing
// the per-chunk LDGSTS issue cost that bound R11/R12.
// ---------------------------------------------------------------------------
__global__ void __launch_bounds__(256, 2) sim_mma_kernel(){
    extern __shared__ __align__(16) char smem[];
    const u32 sb   = smem_u32(smem);
    const int tid  = threadIdx.x;
    const int wid  = tid >> 5;
    const int lane = tid & 31;
    const int n    = blockIdx.y;
    const int blk  = blockIdx.x;
    const int row0 = blk * RT;
    const int mrow = (wid & 3) * 32;          // warp's row offset in tile
    const int ncol = (wid >> 2) * 64;         // warp's col offset in tile

    const char* gA = (const char*)g_qh + (size_t)blk * TILEB;
    const char* gB = (const char*)g_sh + (size_t)n * NT * TILEB;

    if (tid == 0){
        MBAR_INIT(sb + OFF_MBA, 1);
        MBAR_INIT(sb + OFF_MB0, 1);
        MBAR_INIT(sb + OFF_MB1, 1);
    }
    __syncthreads();
    if (tid == 0){
        EXPECT_TX(sb + OFF_MBA, TILEB); BULK_G2S(sb + OFF_A,  gA,         TILEB, sb + OFF_MBA);
        EXPECT_TX(sb + OFF_MB0, TILEB); BULK_G2S(sb + OFF_B0, gB,         TILEB, sb + OFF_MB0);
        EXPECT_TX(sb + OFF_MB1, TILEB); BULK_G2S(sb + OFF_B1, gB + TILEB, TILEB, sb + OFF_MB1);
    }

    const int rA    = lane & 15;              // ldmatrix row-within-frag
    const int khalf = (lane >> 4) * 8;        // ldmatrix k-half
    const u32 swx   = (u32)((rA & 7) << 4);   // SW128 xor term (row low bits)

    // A is tile-loop invariant: hoist all A fragments (32 regs).
    mbar_wait(sb + OFF_MBA, 0);
    u32 af[4][8];
    #pragma unroll
    for (int ks = 0; ks < 4; ks++){
        const u32 colb  = ((u32)((ks * 16 + khalf) * 2)) ^ swx;
        const u32 aaddr = sb + OFF_A + (u32)((mrow + rA) * 128) + colb;
        LDMX4(af[ks],     aaddr);
        LDMX4(af[ks] + 4, aaddr + 2048u);
    }

    // Packed top-3 state: slot s = mf*2 + half; two col-streams per slot.
    const __nv_bfloat162 NI2 = __floats2bfloat162_rn(-INFINITY, -INFINITY);
    __nv_bfloat162 p0[4], p1[4], p2[4];
    #pragma unroll
    for (int s = 0; s < 4; s++){ p0[s] = NI2; p1[s] = NI2; p2[s] = NI2; }

    u32 phase[2] = {0u, 0u};

    for (int t = 0; t < NT; t++){
        const int buf  = t & 1;
        const u32 mb   = sb + (buf ? OFF_MB1 : OFF_MB0);
        mbar_wait(mb, phase[buf]);
        phase[buf] ^= 1u;
        const u32 bbase = sb + (buf ? OFF_B1 : OFF_B0) + (u32)((ncol + rA) * 128);

        // ldB: step = pass*4 + ks -> fragment pair for 32 cols.
        auto ldB = [&](int step, u32* dst){
            const int pass = step >> 2, ks = step & 3;
            const u32 colb  = ((u32)((ks * 16 + khalf) * 2)) ^ swx;
            const u32 baddr = bbase + (u32)(pass * 32 * 128) + colb;
            LDMX4(dst,     baddr);
            LDMX4(dst + 4, baddr + 2048u);
        };
        auto mma8 = [&](float (&c)[2][4][4], int ks, u32* bf){
            MMA16816(c[0][0], af[ks],     bf[0], bf[2]);
            MMA16816(c[0][1], af[ks],     bf[1], bf[3]);
            MMA16816(c[0][2], af[ks],     bf[4], bf[6]);
            MMA16816(c[0][3], af[ks],     bf[5], bf[7]);
            MMA16816(c[1][0], af[ks] + 4, bf[0], bf[2]);
            MMA16816(c[1][1], af[ks] + 4, bf[1], bf[3]);
            MMA16816(c[1][2], af[ks] + 4, bf[4], bf[6]);
            MMA16816(c[1][3], af[ks] + 4, bf[5], bf[7]);
        };
        auto epi_full = [&](float (&c)[2][4][4]){
            #pragma unroll
            for (int mf = 0; mf < 2; mf++)
                #pragma unroll
                for (int nf = 0; nf < 4; nf++){
                    ins3pb(__floats2bfloat162_rn(c[mf][nf][0], c[mf][nf][1]),
                           p0[mf*2],   p1[mf*2],   p2[mf*2]);
                    ins3pb(__floats2bfloat162_rn(c[mf][nf][2], c[mf][nf][3]),
                           p0[mf*2+1], p1[mf*2+1], p2[mf*2+1]);
                }
        };
        auto epi_mask = [&](float (&c)[2][4][4], int pass){
            const int rem = M_ - (NT - 1) * MT;   // 29 valid cols in last tile
            #pragma unroll
            for (int nf = 0; nf < 4; nf++){
                const int col0 = ncol + pass * 32 + nf * 8 + (lane & 3) * 2;
                const bool v0 = col0     < rem;
                const bool v1 = col0 + 1 < rem;
                #pragma unroll
                for (int mf = 0; mf < 2; mf++){
                    ins3pb(__floats2bfloat162_rn(v0 ? c[mf][nf][0] : -INFINITY,
                                                 v1 ? c[mf][nf][1] : -INFINITY),
                           p0[mf*2],   p1[mf*2],   p2[mf*2]);
                    ins3pb(__floats2bfloat162_rn(v0 ? c[mf][nf][2] : -INFINITY,
                                                 v1 ? c[mf][nf][3] : -INFINITY),
                           p0[mf*2+1], p1[mf*2+1], p2[mf*2+1]);
                }
            }
        };

        u32 f0[8], f1[8];
        ldB(0, f0);

        float c0[2][4][4];
        #pragma unroll
        for (int mf = 0; mf < 2; mf++)
            #pragma unroll
            for (int nf = 0; nf < 4; nf++)
                #pragma unroll
                for (int q = 0; q < 4; q++) c0[mf][nf][q] = 0.f;
        ldB(1, f1); mma8(c0, 0, f0);
        ldB(2, f0); mma8(c0, 1, f1);
        ldB(3, f1); mma8(c0, 2, f0);
        ldB(4, f0); mma8(c0, 3, f1);
        if (t < NT - 1) epi_full(c0); else epi_mask(c0, 0);

        float c1[2][4][4];
        #pragma unroll
        for (int mf = 0; mf < 2; mf++)
            #pragma unroll
            for (int nf = 0; nf < 4; nf++)
                #pragma unroll
                for (int q = 0; q < 4; q++) c1[mf][nf][q] = 0.f;
        ldB(5, f1); mma8(c1, 0, f0);
        ldB(6, f0); mma8(c1, 1, f1);
        ldB(7, f1); mma8(c1, 2, f0);
                    mma8(c1, 3, f1);

        // All smem reads of this buffer are done; refill it with ONE bulk copy.
        __syncthreads();
        if (t + 2 < NT && tid == 0){
            const u32 dst = sb + (buf ? OFF_B1 : OFF_B0);
            EXPECT_TX(mb, TILEB);
            BULK_G2S(dst, gB + (size_t)(t + 2) * TILEB, TILEB, mb);
        }
        if (t < NT - 1) epi_full(c1); else epi_mask(c1, 1);
    }

    // Collapse packed streams -> scalar top-3 per slot.
    float s0[4], s1[4], s2[4];
    #pragma unroll
    for (int s = 0; s < 4; s++){
        s0[s] = -INFINITY; s1[s] = -INFINITY; s2[s] = -INFINITY;
        float2 a;
        a = __bfloat1622float2(p0[s]); ins3(a.x, s0[s], s1[s], s2[s]); ins3(a.y, s0[s], s1[s], s2[s]);
        a = __bfloat1622float2(p1[s]); ins3(a.x, s0[s], s1[s], s2[s]); ins3(a.y, s0[s], s1[s], s2[s]);
        a = __bfloat1622float2(p2[s]); ins3(a.x, s0[s], s1[s], s2[s]); ins3(a.y, s0[s], s1[s], s2[s]);
    }
    // Merge across the 4 lanes sharing each row.
    #pragma unroll
    for (int off = 1; off <= 2; off <<= 1){
        #pragma unroll
        for (int s = 0; s < 4; s++){
            float u0 = __shfl_xor_sync(0xffffffffu, s0[s], off);
            float u1 = __shfl_xor_sync(0xffffffffu, s1[s], off);
            float u2 = __shfl_xor_sync(0xffffffffu, s2[s], off);
            ins3(u0, s0[s], s1[s], s2[s]);
            ins3(u1, s0[s], s1[s], s2[s]);
            ins3(u2, s0[s], s1[s], s2[s]);
        }
    }
    // Merge the two column-half warps via smem (A region is dead now).
    float* mrg  = reinterpret_cast<float*>(smem + OFF_A);          // 384 floats
    float* rsum = reinterpret_cast<float*>(smem + OFF_A + 2048);   // 128 floats
    __syncthreads();
    if (wid >= 4 && (lane & 3) == 0){
        #pragma unroll
        for (int s = 0; s < 4; s++){
            int row = mrow + (s >> 1) * 16 + (s & 1) * 8 + (lane >> 2);
            mrg[row * 3 + 0] = s0[s];
            mrg[row * 3 + 1] = s1[s];
            mrg[row * 3 + 2] = s2[s];
        }
    }
    __syncthreads();
    if (wid < 4 && (lane & 3) == 0){
        #pragma unroll
        for (int s = 0; s < 4; s++){
            int row = mrow + (s >> 1) * 16 + (s & 1) * 8 + (lane >> 2);
            ins3(mrg[row * 3 + 0], s0[s], s1[s], s2[s]);
            ins3(mrg[row * 3 + 1], s0[s], s1[s], s2[s]);
            ins3(mrg[row * 3 + 2], s0[s], s1[s], s2[s]);
            rsum[row] = s0[s] + s1[s] + s2[s];   // padded rows naturally give 0
        }
    }
    __syncthreads();
    // Block reduction split by batch-image boundary (<=1 boundary: 441 > 128).
    if (wid == 0){
        const int b0    = row0 / HW;
        const int split = (b0 + 1) * HW - row0;   // may be >= 128 (no boundary)
        float lo = 0.f, hi = 0.f;
        #pragma unroll
        for (int i = 0; i < 4; i++){
            int r = lane + 32 * i;
            float v = rsum[r];
            if (r < split) lo += v; else hi += v;
        }
        #pragma unroll
        for (int o = 16; o; o >>= 1){
            lo += __shfl_down_sync(0xffffffffu, lo, o);
            hi += __shfl_down_sync(0xffffffffu, hi, o);
        }
        if (lane == 0){
            g_part[(n * RB + blk) * 2 + 0] = lo;
            g_part[(n * RB + blk) * 2 + 1] = hi;   // belongs to b0+1 (dropped if 16)
        }
    }
}

// ---------------------------------------------------------------------------
// out[b][n] = sum of partials mapping to b. One block.
// ---------------------------------------------------------------------------
__global__ void reduce_out_kernel(float* __restrict__ out){
    const int tid = threadIdx.x;
    if (tid >= B_ * NCLS) return;
    const int b = tid / NCLS;
    const int n = tid % NCLS;
    float s = 0.f;
    #pragma unroll 8
    for (int blk = 0; blk < RB; blk++){
        int b0 = (blk * RT) / HW;
        float v0 = g_part[(n * RB + blk) * 2 + 0];
        float v1 = g_part[(n * RB + blk) * 2 + 1];
        if (b0 == b)     s += v0;
        if (b0 + 1 == b) s += v1;
    }
    out[tid] = s;
}

extern "C" void kernel_launch(void* const* d_in, const int* in_sizes, int n_in,
                              void* d_out, int out_size){
    const float* x1 = (const float*)d_in[0];   // [16,64,21,21] fp32
    const float* x2 = (const float*)d_in[1];   // [10,64,2205]  fp32
    float* out = (float*)d_out;                // [16,10] fp32

    cudaFuncSetAttribute(sim_mma_kernel,
                         cudaFuncAttributeMaxDynamicSharedMemorySize, SMEM_REQ);
    norm_kernel<<<NU / 32, 256>>>(x1, x2);
    sim_mma_kernel<<<dim3(RB, NCLS), 256, SMEM_REQ>>>();
    reduce_out_kernel<<<1, 192>>>(out);
}